// round 11
// baseline (speedup 1.0000x reference)
#include <cuda_runtime.h>
#include <cstdint>

#define BATCH 256
#define SEQ   64
#define DIMW  1024
#define SDIMW 256
#define MROWS (BATCH*SEQ)   // 16384
#define EPS   1e-5f

// ---------------- scratch (static device globals; no runtime allocation) ----
__device__ float g_gate [MROWS * SDIMW * 2];      // interleaved (dec, drv)
__device__ float g_hs   [MROWS * SDIMW];
__device__ float g_hidden[(size_t)MROWS * DIMW];  // layer-0 hidden (tf32-rounded)
__device__ float g_final [BATCH * SDIMW];
__device__ float g_cstate[BATCH * DIMW];
__device__ float g_pooled[BATCH * DIMW];
__device__ float g_wt[6 * SDIMW * DIMW];   // transposed + tf32-rounded weights

__device__ __forceinline__ float softplusf(float x) {
    float e = __expf(-fabsf(x));
    return fmaxf(x, 0.f) + __logf(1.f + e);
}
__device__ __forceinline__ float tf32r(float f) {
    uint32_t r;
    asm("cvt.rna.tf32.f32 %0, %1;" : "=r"(r) : "f"(f));
    return __uint_as_float(r);
}
__device__ __forceinline__ uint32_t tf32r_bits(uint32_t bits) {
    uint32_t r;
    asm("cvt.rna.tf32.f32 %0, %1;" : "=r"(r) : "f"(__uint_as_float(bits)));
    return r;
}
__device__ __forceinline__ uint32_t smem_u32(const void* p) {
    uint32_t a;
    asm("{ .reg .u64 t; cvta.to.shared.u64 t, %1; cvt.u32.u64 %0, t; }"
        : "=r"(a) : "l"(p));
    return a;
}
__device__ __forceinline__ void ldm_x4(uint32_t addr, uint32_t* r) {
    asm volatile("ldmatrix.sync.aligned.m8n8.x4.shared.b16 {%0,%1,%2,%3}, [%4];"
                 : "=r"(r[0]), "=r"(r[1]), "=r"(r[2]), "=r"(r[3]) : "r"(addr));
}
__device__ __forceinline__ void mma8(float* c, const uint32_t* a, const uint32_t* b) {
    asm volatile("mma.sync.aligned.m16n8k8.row.col.f32.tf32.tf32.f32 "
                 "{%0,%1,%2,%3}, {%4,%5,%6,%7}, {%8,%9}, {%0,%1,%2,%3};"
                 : "+f"(c[0]), "+f"(c[1]), "+f"(c[2]), "+f"(c[3])
                 : "r"(a[0]), "r"(a[1]), "r"(a[2]), "r"(a[3]),
                   "r"(b[0]), "r"(b[1]));
}
__device__ __forceinline__ void cp16(uint32_t dst, const void* src) {
    asm volatile("cp.async.cg.shared.global [%0], [%1], 16;"
                 :: "r"(dst), "l"(src) : "memory");
}
__device__ __forceinline__ void cp_commit() {
    asm volatile("cp.async.commit_group;" ::: "memory");
}

// ---------------------------------------------------------------------------
// 6 weight transposes (+ tf32 round) in one launch.
// ---------------------------------------------------------------------------
__global__ void transpose6_kernel(const float* __restrict__ Wd,
                                  const float* __restrict__ Wi,
                                  const float* __restrict__ Wo,
                                  float* __restrict__ wt) {
    __shared__ float t[32][33];
    const int z = blockIdx.z;
    const int layer = z / 3, mat = z % 3;
    const size_t WSZ = (size_t)SDIMW * DIMW;
    const float* src = (mat == 0 ? Wd : (mat == 1 ? Wi : Wo)) + layer * WSZ;
    float* dst = wt + (size_t)z * WSZ;
    int R, C, c0, r0;
    if (mat == 2) { R = SDIMW; C = DIMW; c0 = blockIdx.y * 32; r0 = blockIdx.x * 32; }
    else          { R = DIMW; C = SDIMW; c0 = blockIdx.x * 32; r0 = blockIdx.y * 32; }
    const int tx = threadIdx.x, ty = threadIdx.y;
    #pragma unroll
    for (int k = 0; k < 4; k++)
        t[ty + 8 * k][tx] = src[(size_t)(r0 + ty + 8 * k) * C + c0 + tx];
    __syncthreads();
    #pragma unroll
    for (int k = 0; k < 4; k++)
        dst[(size_t)(c0 + ty + 8 * k) * R + r0 + tx] = tf32r(t[tx][ty + 8 * k]);
}

// ---------------------------------------------------------------------------
// proj with cp.async 3-stage: gate[M,256,2] = f(X[M,1024] x {WdT,WiT}^T)
// CTA: 128m x 64n(dual). 8 warps 4(m) x 2(n), 32x32 warp tiles, BK=32.
// cvtA: tf32-round A fragments post-ldmatrix (layer 0, raw X input).
// ---------------------------------------------------------------------------
#define PJ_SMEM (98304 + 3 * 64 * 4)
__global__ __launch_bounds__(256)
void proj_mma_kernel(const float* __restrict__ X,
                     const float* __restrict__ WdT, const float* __restrict__ WiT,
                     const float* __restrict__ bd, const float* __restrict__ bi,
                     const float* __restrict__ A_log,
                     float* __restrict__ gate, int cvtA)
{
    extern __shared__ char smem[];
    const uint32_t sbase = smem_u32(smem);
    const int tid = threadIdx.x, wid = tid >> 5, lane = tid & 31;
    const int wm = wid & 3, wn = wid >> 2;
    const int m0 = blockIdx.y * 128, n0 = blockIdx.x * 64;

    float* sbd = (float*)(smem + 98304);
    float* sbi = sbd + 64;
    float* ssa = sbi + 64;
    if (tid < 64) {
        sbd[tid] = bd[n0 + tid];
        sbi[tid] = bi[n0 + tid];
        ssa[tid] = softplusf(A_log[n0 + tid]);
    }

    const int lrow4 = tid >> 3, lc16 = tid & 7;
    const int swz = lane & 7, sel = lane >> 3;
    const int selr = (sel & 1) * 8, selc = sel >> 1;

    uint32_t aRow[2], bRow[4];
    #pragma unroll
    for (int mt = 0; mt < 2; mt++)
        aRow[mt] = (uint32_t)((wm * 32 + mt * 16 + selr + swz) * 128);
    #pragma unroll
    for (int nt = 0; nt < 4; nt++)
        bRow[nt] = (uint32_t)((wn * 32 + nt * 8 + swz) * 128);

    const uint32_t ldOffA[4] = {
        (uint32_t)((lrow4 + 0)  * 128 + ((lc16 ^ ((lrow4 + 0)  & 7)) << 4)),
        (uint32_t)((lrow4 + 32) * 128 + ((lc16 ^ ((lrow4 + 32) & 7)) << 4)),
        (uint32_t)((lrow4 + 64) * 128 + ((lc16 ^ ((lrow4 + 64) & 7)) << 4)),
        (uint32_t)((lrow4 + 96) * 128 + ((lc16 ^ ((lrow4 + 96) & 7)) << 4))
    };
    const float* aSrc = X   + (size_t)(m0 + lrow4) * DIMW + lc16 * 4;
    const float* dSrc = WdT + (size_t)(n0 + lrow4) * DIMW + lc16 * 4;
    const float* iSrc = WiT + (size_t)(n0 + lrow4) * DIMW + lc16 * 4;

    #define PJ_ISSUE(kt_) do {                                                  \
        const int _s = (kt_) % 3;                                               \
        const int _k0 = (kt_) * 32;                                             \
        _Pragma("unroll")                                                       \
        for (int i = 0; i < 4; i++)                                             \
            cp16(sbase + _s * 16384 + ldOffA[i],                                \
                 aSrc + (size_t)(i * 32) * DIMW + _k0);                         \
        _Pragma("unroll")                                                       \
        for (int i = 0; i < 2; i++) {                                           \
            cp16(sbase + 49152 + _s * 8192 + ldOffA[i],                         \
                 dSrc + (size_t)(i * 32) * DIMW + _k0);                         \
            cp16(sbase + 73728 + _s * 8192 + ldOffA[i],                         \
                 iSrc + (size_t)(i * 32) * DIMW + _k0);                         \
        }                                                                       \
        cp_commit();                                                            \
    } while (0)

    PJ_ISSUE(0);
    PJ_ISSUE(1);

    float accD[2][4][4] = {};
    float accI[2][4][4] = {};

    const int KT = DIMW / 32;   // 32
    for (int kt = 0; kt < KT; kt++) {
        if (kt == KT - 1)
            asm volatile("cp.async.wait_group 0;" ::: "memory");
        else
            asm volatile("cp.async.wait_group 1;" ::: "memory");
        __syncthreads();
        if (kt + 2 < KT) PJ_ISSUE(kt + 2);

        const uint32_t Asm  = sbase + (kt % 3) * 16384;
        const uint32_t Bdsm = sbase + 49152 + (kt % 3) * 8192;
        const uint32_t Bism = sbase + 73728 + (kt % 3) * 8192;

        uint32_t af[2][4][4];
        #pragma unroll
        for (int mt = 0; mt < 2; mt++)
            #pragma unroll
            for (int kk = 0; kk < 4; kk++)
                ldm_x4(Asm + aRow[mt] + (((kk * 2 + selc) ^ swz) << 4), af[mt][kk]);

        if (cvtA) {
            #pragma unroll
            for (int mt = 0; mt < 2; mt++)
                #pragma unroll
                for (int kk = 0; kk < 4; kk++)
                    #pragma unroll
                    for (int r = 0; r < 4; r++)
                        af[mt][kk][r] = tf32r_bits(af[mt][kk][r]);
        }

        #pragma unroll
        for (int out = 0; out < 2; out++) {
            const uint32_t Bsm = out ? Bism : Bdsm;
            #pragma unroll
            for (int kh = 0; kh < 2; kh++) {
                uint32_t bf[4][4];
                #pragma unroll
                for (int nt = 0; nt < 4; nt++)
                    ldm_x4(Bsm + bRow[nt] + (((kh * 4 + sel) ^ swz) << 4), bf[nt]);
                #pragma unroll
                for (int kk2 = 0; kk2 < 2; kk2++)
                    #pragma unroll
                    for (int mt = 0; mt < 2; mt++)
                        #pragma unroll
                        for (int nt = 0; nt < 4; nt++)
                            mma8(out ? accI[mt][nt] : accD[mt][nt],
                                 af[mt][kh * 2 + kk2], &bf[nt][kk2 * 2]);
            }
        }
    }

    // epilogue: interleaved gate store (dec0, drv0, dec1, drv1) as float4
    const int g = lane >> 2, t = lane & 3;
    #pragma unroll
    for (int mt = 0; mt < 2; mt++) {
        const int row0 = m0 + wm * 32 + mt * 16 + g;
        #pragma unroll
        for (int nt = 0; nt < 4; nt++) {
            const int nl = wn * 32 + nt * 8 + 2 * t;
            const float b0 = sbd[nl], b1 = sbd[nl + 1];
            const float i0 = sbi[nl], i1 = sbi[nl + 1];
            const float a0 = ssa[nl], a1 = ssa[nl + 1];
            #pragma unroll
            for (int rh = 0; rh < 2; rh++) {
                const int row = row0 + rh * 8;
                const float de0 = softplusf(accD[mt][nt][rh * 2 + 0] + b0);
                const float de1 = softplusf(accD[mt][nt][rh * 2 + 1] + b1);
                float4 gv;
                gv.x = __expf(-de0 * a0);
                gv.y = de0 * (accI[mt][nt][rh * 2 + 0] + i0);
                gv.z = __expf(-de1 * a1);
                gv.w = de1 * (accI[mt][nt][rh * 2 + 1] + i1);
                *(float4*)(gate + ((size_t)row * SDIMW + n0 + nl) * 2) = gv;
            }
        }
    }
}

// ---------------------------------------------------------------------------
// outgemm with cp.async 3-stage (proven). roundOut: write tf32-rounded.
// ---------------------------------------------------------------------------
#define OG_SMEM (98304 + 128 * 4)
__global__ __launch_bounds__(256)
void outgemm_mma_kernel(const float* __restrict__ HS, const float* __restrict__ WoT,
                        const float* __restrict__ bo, const float* __restrict__ cs,
                        float* __restrict__ out, float* __restrict__ pooled,
                        int roundOut)
{
    extern __shared__ char smem[];
    const uint32_t sbase = smem_u32(smem);
    const int tid = threadIdx.x, wid = tid >> 5, lane = tid & 31;
    const int wm = wid & 1, wn = wid >> 1;
    const int m0 = blockIdx.y * 128, n0 = blockIdx.x * 128;

    float* sbo = (float*)(smem + 98304);
    if (tid < 128) sbo[tid] = bo[n0 + tid];

    const int lrow4 = tid >> 3, lc16 = tid & 7;
    const int swz = lane & 7, sel = lane >> 3;
    const int selr = (sel & 1) * 8, selc = sel >> 1;

    uint32_t aRow[4], bRow[4];
    #pragma unroll
    for (int mt = 0; mt < 4; mt++)
        aRow[mt] = (uint32_t)((wm * 64 + mt * 16 + selr + swz) * 128);
    #pragma unroll
    for (int nt = 0; nt < 4; nt++)
        bRow[nt] = (uint32_t)((wn * 32 + nt * 8 + swz) * 128);

    const uint32_t ldOff[4] = {
        (uint32_t)((lrow4 + 0)  * 128 + ((lc16 ^ ((lrow4 + 0)  & 7)) << 4)),
        (uint32_t)((lrow4 + 32) * 128 + ((lc16 ^ ((lrow4 + 32) & 7)) << 4)),
        (uint32_t)((lrow4 + 64) * 128 + ((lc16 ^ ((lrow4 + 64) & 7)) << 4)),
        (uint32_t)((lrow4 + 96) * 128 + ((lc16 ^ ((lrow4 + 96) & 7)) << 4))
    };
    const float* aSrc = HS  + (size_t)(m0 + lrow4) * SDIMW + lc16 * 4;
    const float* bSrc = WoT + (size_t)(n0 + lrow4) * SDIMW + lc16 * 4;

    #define OG_ISSUE(kt_) do {                                                  \
        const int _s = (kt_) % 3;                                               \
        const int _k0 = (kt_) * 32;                                             \
        _Pragma("unroll")                                                       \
        for (int i = 0; i < 4; i++) {                                           \
            cp16(sbase + _s * 16384 + ldOff[i],                                 \
                 aSrc + (size_t)(i * 32) * SDIMW + _k0);                        \
            cp16(sbase + 49152 + _s * 16384 + ldOff[i],                         \
                 bSrc + (size_t)(i * 32) * SDIMW + _k0);                        \
        }                                                                       \
        cp_commit();                                                            \
    } while (0)

    OG_ISSUE(0);
    OG_ISSUE(1);

    float acc[4][4][4] = {};

    const int KT = SDIMW / 32;   // 8
    for (int kt = 0; kt < KT; kt++) {
        if (kt == KT - 1)
            asm volatile("cp.async.wait_group 0;" ::: "memory");
        else
            asm volatile("cp.async.wait_group 1;" ::: "memory");
        __syncthreads();
        if (kt + 2 < KT) OG_ISSUE(kt + 2);

        const uint32_t Asm = sbase + (kt % 3) * 16384;
        const uint32_t Bsm = sbase + 49152 + (kt % 3) * 16384;

        #pragma unroll
        for (int kh = 0; kh < 2; kh++) {
            uint32_t bf[4][4];
            #pragma unroll
            for (int nt = 0; nt < 4; nt++)
                ldm_x4(Bsm + bRow[nt] + (((kh * 4 + sel) ^ swz) << 4), bf[nt]);
            #pragma unroll
            for (int kk2 = 0; kk2 < 2; kk2++) {
                const int kk = kh * 2 + kk2;
                uint32_t af[4][4];
                #pragma unroll
                for (int mt = 0; mt < 4; mt++)
                    ldm_x4(Asm + aRow[mt] + (((kk * 2 + selc) ^ swz) << 4), af[mt]);
                #pragma unroll
                for (int mt = 0; mt < 4; mt++)
                    #pragma unroll
                    for (int nt = 0; nt < 4; nt++)
                        mma8(acc[mt][nt], af[mt], &bf[nt][kk2 * 2]);
            }
        }
    }

    const int g = lane >> 2, t = lane & 3;
    const int bb = blockIdx.y * 2 + wm;
    float psum[4][2];
    #pragma unroll
    for (int nt = 0; nt < 4; nt++) {
        const int nl = wn * 32 + nt * 8 + 2 * t;
        const float2 cv = *(const float2*)(cs + (size_t)bb * DIMW + n0 + nl);
        const float add0 = sbo[nl] + cv.x;
        const float add1 = sbo[nl + 1] + cv.y;
        float s0 = 0.f, s1 = 0.f;
        #pragma unroll
        for (int mt = 0; mt < 4; mt++) {
            const int row0 = m0 + wm * 64 + mt * 16 + g;
            #pragma unroll
            for (int rh = 0; rh < 2; rh++) {
                const int row = row0 + rh * 8;
                float2 ov = make_float2(acc[mt][nt][rh * 2 + 0] + add0,
                                        acc[mt][nt][rh * 2 + 1] + add1);
                if (roundOut) { ov.x = tf32r(ov.x); ov.y = tf32r(ov.y); }
                *(float2*)(out + (size_t)row * DIMW + n0 + nl) = ov;
                s0 += ov.x; s1 += ov.y;
            }
        }
        psum[nt][0] = s0; psum[nt][1] = s1;
    }
    if (pooled) {
        #pragma unroll
        for (int nt = 0; nt < 4; nt++) {
            #pragma unroll
            for (int o = 4; o < 32; o <<= 1) {
                psum[nt][0] += __shfl_xor_sync(0xffffffffu, psum[nt][0], o);
                psum[nt][1] += __shfl_xor_sync(0xffffffffu, psum[nt][1], o);
            }
        }
        if (lane < 4) {
            #pragma unroll
            for (int nt = 0; nt < 4; nt++) {
                const int nl = wn * 32 + nt * 8 + 2 * lane;
                float2 pv = make_float2(psum[nt][0] * (1.f / (float)SEQ),
                                        psum[nt][1] * (1.f / (float)SEQ));
                *(float2*)(pooled + (size_t)bb * DIMW + n0 + nl) = pv;
            }
        }
    }
}

// ---------------------------------------------------------------------------
// scan over interleaved gate stream. 512 blocks x 128 threads.
// ---------------------------------------------------------------------------
__global__ __launch_bounds__(128)
void scan_kernel(const float* __restrict__ gate,
                 float* __restrict__ hs, float* __restrict__ fin)
{
    const int b = blockIdx.x >> 1;
    const int n = ((blockIdx.x & 1) << 7) + threadIdx.x;
    const size_t gbase = ((size_t)b * SEQ * SDIMW + n) * 2;
    const size_t hbase = (size_t)b * SEQ * SDIMW + n;
    float h = 0.f;
    #pragma unroll 8
    for (int s = 0; s < SEQ; s++) {
        const float2 gd = *(const float2*)(gate + gbase + (size_t)s * SDIMW * 2);
        h = fmaf(gd.x, h, gd.y);
        hs[hbase + (size_t)s * SDIMW] = tf32r(h);
    }
    fin[b * SDIMW + n] = h;
}

// ---------------------------------------------------------------------------
#define CS_BG 8
__global__ __launch_bounds__(128)
void cstate_kernel(const float* __restrict__ fin, const float* __restrict__ Ws,
                   const float* __restrict__ bs, float* __restrict__ cs)
{
    __shared__ float sf[CS_BG][SDIMW];
    const int d = blockIdx.x * 128 + threadIdx.x;
    const int b0 = blockIdx.y * CS_BG;
    #pragma unroll
    for (int i = 0; i < 4; i++) {
        const int idx = threadIdx.x + i * 128;
        const int row = idx >> 6, c4 = idx & 63;
        *(float4*)&sf[row][c4 * 4] =
            *(const float4*)(fin + (size_t)(b0 + row) * SDIMW + c4 * 4);
    }
    __syncthreads();

    float acc[CS_BG] = {};
    for (int n = 0; n < SDIMW; n += 4) {
        const float w0 = Ws[(size_t)(n + 0) * DIMW + d];
        const float w1 = Ws[(size_t)(n + 1) * DIMW + d];
        const float w2 = Ws[(size_t)(n + 2) * DIMW + d];
        const float w3 = Ws[(size_t)(n + 3) * DIMW + d];
        #pragma unroll
        for (int b = 0; b < CS_BG; b++) {
            const float4 s = *(const float4*)&sf[b][n];
            acc[b] = fmaf(s.x, w0, acc[b]);
            acc[b] = fmaf(s.y, w1, acc[b]);
            acc[b] = fmaf(s.z, w2, acc[b]);
            acc[b] = fmaf(s.w, w3, acc[b]);
        }
    }
    const float bsv = bs[d];
    #pragma unroll
    for (int b = 0; b < CS_BG; b++)
        cs[(size_t)(b0 + b) * DIMW + d] = acc[b] + bsv;
}

// ---------------------------------------------------------------------------
__global__ __launch_bounds__(256)
void final_kernel(const float* __restrict__ pmean, const float* __restrict__ cs,
                  const float* __restrict__ gamma, const float* __restrict__ beta,
                  float* __restrict__ out)
{
    const int b = blockIdx.x;
    const int tid = threadIdx.x;

    float pooled[4];
    float lsum = 0.f, lsq = 0.f;
    #pragma unroll
    for (int i = 0; i < 4; i++) {
        const int d = i * 256 + tid;
        float p = cs[(size_t)b * DIMW + d] + pmean[(size_t)b * DIMW + d];
        pooled[i] = p;
        lsum += p;
        lsq  += p * p;
    }

    __shared__ float s1[8], s2[8];
    #pragma unroll
    for (int o = 16; o > 0; o >>= 1) {
        lsum += __shfl_xor_sync(0xffffffffu, lsum, o);
        lsq  += __shfl_xor_sync(0xffffffffu, lsq,  o);
    }
    if ((tid & 31) == 0) { s1[tid >> 5] = lsum; s2[tid >> 5] = lsq; }
    __syncthreads();
    float tsum = 0.f, tsq = 0.f;
    #pragma unroll
    for (int w = 0; w < 8; w++) { tsum += s1[w]; tsq += s2[w]; }

    const float mu  = tsum * (1.f / (float)DIMW);
    const float var = tsq * (1.f / (float)DIMW) - mu * mu;
    const float rstd = rsqrtf(var + EPS);

    #pragma unroll
    for (int i = 0; i < 4; i++) {
        const int d = i * 256 + tid;
        out[(size_t)b * DIMW + d] = (pooled[i] - mu) * rstd * gamma[d] + beta[d];
    }
}

// ---------------------------------------------------------------------------
extern "C" void kernel_launch(void* const* d_in, const int* in_sizes, int n_in,
                              void* d_out, int out_size)
{
    const float* X     = (const float*)d_in[0];
    const float* Wd    = (const float*)d_in[1];
    const float* bd    = (const float*)d_in[2];
    const float* Wi    = (const float*)d_in[3];
    const float* bi    = (const float*)d_in[4];
    const float* A_log = (const float*)d_in[5];
    const float* Wo    = (const float*)d_in[6];
    const float* bo    = (const float*)d_in[7];
    const float* Ws    = (const float*)d_in[8];
    const float* bs    = (const float*)d_in[9];
    const float* gamma = (const float*)d_in[10];
    const float* beta  = (const float*)d_in[11];

    float* out_repr   = (float*)d_out;                         // [B, D]
    float* out_hidden = (float*)d_out + (size_t)BATCH * DIMW;  // [B, S, D]

    float *p_gate, *p_hs, *p_hidden, *p_final, *p_cstate, *p_pooled, *p_wt;
    cudaGetSymbolAddress((void**)&p_gate,   g_gate);
    cudaGetSymbolAddress((void**)&p_hs,     g_hs);
    cudaGetSymbolAddress((void**)&p_hidden, g_hidden);
    cudaGetSymbolAddress((void**)&p_final,  g_final);
    cudaGetSymbolAddress((void**)&p_cstate, g_cstate);
    cudaGetSymbolAddress((void**)&p_pooled, g_pooled);
    cudaGetSymbolAddress((void**)&p_wt,     g_wt);

    cudaFuncSetAttribute(proj_mma_kernel,
                         cudaFuncAttributeMaxDynamicSharedMemorySize, PJ_SMEM);
    cudaFuncSetAttribute(outgemm_mma_kernel,
                         cudaFuncAttributeMaxDynamicSharedMemorySize, OG_SMEM);

    const size_t WSZ = (size_t)SDIMW * DIMW;
    float* WdT0 = p_wt + 0 * WSZ;
    float* WiT0 = p_wt + 1 * WSZ;
    float* WoT0 = p_wt + 2 * WSZ;
    float* WdT1 = p_wt + 3 * WSZ;
    float* WiT1 = p_wt + 4 * WSZ;
    float* WoT1 = p_wt + 5 * WSZ;

    transpose6_kernel<<<dim3(8, 32, 6), dim3(32, 8)>>>(Wd, Wi, Wo, p_wt);

    const dim3 pjGrid(SDIMW / 64, MROWS / 128);    // (4, 128)
    const dim3 ogGrid(DIMW / 128, MROWS / 128);    // (8, 128)
    const dim3 csGrid(DIMW / 128, BATCH / CS_BG);  // (8, 32)

    // ---------------- layer 0 (raw X; fragments cvt'd in-kernel) -----------
    proj_mma_kernel<<<pjGrid, 256, PJ_SMEM>>>(X, WdT0, WiT0, bd, bi, A_log,
                                              p_gate, 1);
    scan_kernel<<<BATCH * 2, 128>>>(p_gate, p_hs, p_final);
    cstate_kernel<<<csGrid, 128>>>(p_final, Ws, bs, p_cstate);
    outgemm_mma_kernel<<<ogGrid, 256, OG_SMEM>>>(p_hs, WoT0, bo, p_cstate,
                                                 p_hidden, nullptr, 1);

    // ---------------- layer 1 (hidden already tf32-rounded) ----------------
    proj_mma_kernel<<<pjGrid, 256, PJ_SMEM>>>(p_hidden, WdT1, WiT1, bd + SDIMW,
                                              bi + SDIMW, A_log + SDIMW,
                                              p_gate, 0);
    scan_kernel<<<BATCH * 2, 128>>>(p_gate, p_hs, p_final);
    cstate_kernel<<<csGrid, 128>>>(p_final, Ws + WSZ, bs + DIMW, p_cstate);
    outgemm_mma_kernel<<<ogGrid, 256, OG_SMEM>>>(p_hs, WoT1, bo + DIMW, p_cstate,
                                                 out_hidden, p_pooled, 0);

    // ---------------- LayerNorm ----------------
    final_kernel<<<BATCH, 256>>>(p_pooled, p_cstate, gamma, beta, out_repr);
}

// round 12
// speedup vs baseline: 1.0727x; 1.0727x over previous
#include <cuda_runtime.h>
#include <cstdint>

#define BATCH 256
#define SEQ   64
#define DIMW  1024
#define SDIMW 256
#define MROWS (BATCH*SEQ)   // 16384
#define EPS   1e-5f

// ---------------- scratch (static device globals; no runtime allocation) ----
__device__ float g_decay[MROWS * SDIMW];
__device__ float g_drive[MROWS * SDIMW];
__device__ float g_hs   [MROWS * SDIMW];
__device__ float g_hidden[(size_t)MROWS * DIMW];  // layer-0 hidden (tf32-rounded)
__device__ float g_xr    [(size_t)MROWS * DIMW];  // tf32-rounded X
__device__ float g_final [BATCH * SDIMW];
__device__ float g_cstate[BATCH * DIMW];
__device__ float g_pooled[BATCH * DIMW];
__device__ float g_wt[6 * SDIMW * DIMW];   // transposed + tf32-rounded weights

__device__ __forceinline__ float softplusf(float x) {
    float e = __expf(-fabsf(x));
    return fmaxf(x, 0.f) + __logf(1.f + e);
}
__device__ __forceinline__ float tf32r(float f) {
    uint32_t r;
    asm("cvt.rna.tf32.f32 %0, %1;" : "=r"(r) : "f"(f));
    return __uint_as_float(r);
}
__device__ __forceinline__ float4 tf32r4(float4 v) {
    return make_float4(tf32r(v.x), tf32r(v.y), tf32r(v.z), tf32r(v.w));
}
__device__ __forceinline__ uint32_t smem_u32(const void* p) {
    uint32_t a;
    asm("{ .reg .u64 t; cvta.to.shared.u64 t, %1; cvt.u32.u64 %0, t; }"
        : "=r"(a) : "l"(p));
    return a;
}
__device__ __forceinline__ void ldm_x4(uint32_t addr, uint32_t* r) {
    asm volatile("ldmatrix.sync.aligned.m8n8.x4.shared.b16 {%0,%1,%2,%3}, [%4];"
                 : "=r"(r[0]), "=r"(r[1]), "=r"(r[2]), "=r"(r[3]) : "r"(addr));
}
__device__ __forceinline__ void mma8(float* c, const uint32_t* a, const uint32_t* b) {
    asm volatile("mma.sync.aligned.m16n8k8.row.col.f32.tf32.tf32.f32 "
                 "{%0,%1,%2,%3}, {%4,%5,%6,%7}, {%8,%9}, {%0,%1,%2,%3};"
                 : "+f"(c[0]), "+f"(c[1]), "+f"(c[2]), "+f"(c[3])
                 : "r"(a[0]), "r"(a[1]), "r"(a[2]), "r"(a[3]),
                   "r"(b[0]), "r"(b[1]));
}
__device__ __forceinline__ void cp16(uint32_t dst, const void* src) {
    asm volatile("cp.async.cg.shared.global [%0], [%1], 16;"
                 :: "r"(dst), "l"(src) : "memory");
}
__device__ __forceinline__ void cp_commit() {
    asm volatile("cp.async.commit_group;" ::: "memory");
}

// ---------------------------------------------------------------------------
// elementwise tf32 rounding (X -> Xr)
// ---------------------------------------------------------------------------
__global__ __launch_bounds__(256)
void round_kernel(const float4* __restrict__ in, float4* __restrict__ out) {
    const size_t i = (size_t)blockIdx.x * 256 + threadIdx.x;
    out[i] = tf32r4(in[i]);
}

// ---------------------------------------------------------------------------
// 6 weight transposes (+ tf32 round) in one launch.
// ---------------------------------------------------------------------------
__global__ void transpose6_kernel(const float* __restrict__ Wd,
                                  const float* __restrict__ Wi,
                                  const float* __restrict__ Wo,
                                  float* __restrict__ wt) {
    __shared__ float t[32][33];
    const int z = blockIdx.z;
    const int layer = z / 3, mat = z % 3;
    const size_t WSZ = (size_t)SDIMW * DIMW;
    const float* src = (mat == 0 ? Wd : (mat == 1 ? Wi : Wo)) + layer * WSZ;
    float* dst = wt + (size_t)z * WSZ;
    int R, C, c0, r0;
    if (mat == 2) { R = SDIMW; C = DIMW; c0 = blockIdx.y * 32; r0 = blockIdx.x * 32; }
    else          { R = DIMW; C = SDIMW; c0 = blockIdx.x * 32; r0 = blockIdx.y * 32; }
    const int tx = threadIdx.x, ty = threadIdx.y;
    #pragma unroll
    for (int k = 0; k < 4; k++)
        t[ty + 8 * k][tx] = src[(size_t)(r0 + ty + 8 * k) * C + c0 + tx];
    __syncthreads();
    #pragma unroll
    for (int k = 0; k < 4; k++)
        dst[(size_t)(c0 + ty + 8 * k) * R + r0 + tx] = tf32r(t[tx][ty + 8 * k]);
}

// ---------------------------------------------------------------------------
// proj with cp.async 3-stage (R9-proven): decay/drive[M,256]
// ---------------------------------------------------------------------------
#define PJ_SMEM (98304 + 3 * 64 * 4)
__global__ __launch_bounds__(256)
void proj_mma_kernel(const float* __restrict__ X,
                     const float* __restrict__ WdT, const float* __restrict__ WiT,
                     const float* __restrict__ bd, const float* __restrict__ bi,
                     const float* __restrict__ A_log,
                     float* __restrict__ decay, float* __restrict__ drive)
{
    extern __shared__ char smem[];
    const uint32_t sbase = smem_u32(smem);
    const int tid = threadIdx.x, wid = tid >> 5, lane = tid & 31;
    const int wm = wid & 3, wn = wid >> 2;
    const int m0 = blockIdx.y * 128, n0 = blockIdx.x * 64;

    float* sbd = (float*)(smem + 98304);
    float* sbi = sbd + 64;
    float* ssa = sbi + 64;
    if (tid < 64) {
        sbd[tid] = bd[n0 + tid];
        sbi[tid] = bi[n0 + tid];
        ssa[tid] = softplusf(A_log[n0 + tid]);
    }

    const int lrow4 = tid >> 3, lc16 = tid & 7;
    const int swz = lane & 7, sel = lane >> 3;
    const int selr = (sel & 1) * 8, selc = sel >> 1;

    uint32_t aRow[2], bRow[4];
    #pragma unroll
    for (int mt = 0; mt < 2; mt++)
        aRow[mt] = (uint32_t)((wm * 32 + mt * 16 + selr + swz) * 128);
    #pragma unroll
    for (int nt = 0; nt < 4; nt++)
        bRow[nt] = (uint32_t)((wn * 32 + nt * 8 + swz) * 128);

    const uint32_t ldOffA[4] = {
        (uint32_t)((lrow4 + 0)  * 128 + ((lc16 ^ ((lrow4 + 0)  & 7)) << 4)),
        (uint32_t)((lrow4 + 32) * 128 + ((lc16 ^ ((lrow4 + 32) & 7)) << 4)),
        (uint32_t)((lrow4 + 64) * 128 + ((lc16 ^ ((lrow4 + 64) & 7)) << 4)),
        (uint32_t)((lrow4 + 96) * 128 + ((lc16 ^ ((lrow4 + 96) & 7)) << 4))
    };
    const float* aSrc = X   + (size_t)(m0 + lrow4) * DIMW + lc16 * 4;
    const float* dSrc = WdT + (size_t)(n0 + lrow4) * DIMW + lc16 * 4;
    const float* iSrc = WiT + (size_t)(n0 + lrow4) * DIMW + lc16 * 4;

    #define PJ_ISSUE(kt_) do {                                                  \
        const int _s = (kt_) % 3;                                               \
        const int _k0 = (kt_) * 32;                                             \
        _Pragma("unroll")                                                       \
        for (int i = 0; i < 4; i++)                                             \
            cp16(sbase + _s * 16384 + ldOffA[i],                                \
                 aSrc + (size_t)(i * 32) * DIMW + _k0);                         \
        _Pragma("unroll")                                                       \
        for (int i = 0; i < 2; i++) {                                           \
            cp16(sbase + 49152 + _s * 8192 + ldOffA[i],                         \
                 dSrc + (size_t)(i * 32) * DIMW + _k0);                         \
            cp16(sbase + 73728 + _s * 8192 + ldOffA[i],                         \
                 iSrc + (size_t)(i * 32) * DIMW + _k0);                         \
        }                                                                       \
        cp_commit();                                                            \
    } while (0)

    PJ_ISSUE(0);
    PJ_ISSUE(1);

    float accD[2][4][4] = {};
    float accI[2][4][4] = {};

    const int KT = DIMW / 32;   // 32
    for (int kt = 0; kt < KT; kt++) {
        if (kt == KT - 1)
            asm volatile("cp.async.wait_group 0;" ::: "memory");
        else
            asm volatile("cp.async.wait_group 1;" ::: "memory");
        __syncthreads();
        if (kt + 2 < KT) PJ_ISSUE(kt + 2);

        const uint32_t Asm  = sbase + (kt % 3) * 16384;
        const uint32_t Bdsm = sbase + 49152 + (kt % 3) * 8192;
        const uint32_t Bism = sbase + 73728 + (kt % 3) * 8192;

        uint32_t af[2][4][4];
        #pragma unroll
        for (int mt = 0; mt < 2; mt++)
            #pragma unroll
            for (int kk = 0; kk < 4; kk++)
                ldm_x4(Asm + aRow[mt] + (((kk * 2 + selc) ^ swz) << 4), af[mt][kk]);

        #pragma unroll
        for (int out = 0; out < 2; out++) {
            const uint32_t Bsm = out ? Bism : Bdsm;
            #pragma unroll
            for (int kh = 0; kh < 2; kh++) {
                uint32_t bf[4][4];
                #pragma unroll
                for (int nt = 0; nt < 4; nt++)
                    ldm_x4(Bsm + bRow[nt] + (((kh * 4 + sel) ^ swz) << 4), bf[nt]);
                #pragma unroll
                for (int kk2 = 0; kk2 < 2; kk2++)
                    #pragma unroll
                    for (int mt = 0; mt < 2; mt++)
                        #pragma unroll
                        for (int nt = 0; nt < 4; nt++)
                            mma8(out ? accI[mt][nt] : accD[mt][nt],
                                 af[mt][kh * 2 + kk2], &bf[nt][kk2 * 2]);
            }
        }
    }

    const int g = lane >> 2, t = lane & 3;
    #pragma unroll
    for (int mt = 0; mt < 2; mt++) {
        const int row0 = m0 + wm * 32 + mt * 16 + g;
        #pragma unroll
        for (int nt = 0; nt < 4; nt++) {
            const int nl = wn * 32 + nt * 8 + 2 * t;
            const float b0 = sbd[nl], b1 = sbd[nl + 1];
            const float i0 = sbi[nl], i1 = sbi[nl + 1];
            const float a0 = ssa[nl], a1 = ssa[nl + 1];
            #pragma unroll
            for (int rh = 0; rh < 2; rh++) {
                const int row = row0 + rh * 8;
                const float de0 = softplusf(accD[mt][nt][rh * 2 + 0] + b0);
                const float de1 = softplusf(accD[mt][nt][rh * 2 + 1] + b1);
                float2 dec = make_float2(__expf(-de0 * a0), __expf(-de1 * a1));
                float2 drv = make_float2(de0 * (accI[mt][nt][rh * 2 + 0] + i0),
                                         de1 * (accI[mt][nt][rh * 2 + 1] + i1));
                *(float2*)(decay + (size_t)row * SDIMW + n0 + nl) = dec;
                *(float2*)(drive + (size_t)row * SDIMW + n0 + nl) = drv;
            }
        }
    }
}

// ---------------------------------------------------------------------------
// outgemm with cp.async 3-stage (R9-proven). roundOut: tf32-rounded output.
// ---------------------------------------------------------------------------
#define OG_SMEM (98304 + 128 * 4)
__global__ __launch_bounds__(256)
void outgemm_mma_kernel(const float* __restrict__ HS, const float* __restrict__ WoT,
                        const float* __restrict__ bo, const float* __restrict__ cs,
                        float* __restrict__ out, float* __restrict__ pooled,
                        int roundOut)
{
    extern __shared__ char smem[];
    const uint32_t sbase = smem_u32(smem);
    const int tid = threadIdx.x, wid = tid >> 5, lane = tid & 31;
    const int wm = wid & 1, wn = wid >> 1;
    const int m0 = blockIdx.y * 128, n0 = blockIdx.x * 128;

    float* sbo = (float*)(smem + 98304);
    if (tid < 128) sbo[tid] = bo[n0 + tid];

    const int lrow4 = tid >> 3, lc16 = tid & 7;
    const int swz = lane & 7, sel = lane >> 3;
    const int selr = (sel & 1) * 8, selc = sel >> 1;

    uint32_t aRow[4], bRow[4];
    #pragma unroll
    for (int mt = 0; mt < 4; mt++)
        aRow[mt] = (uint32_t)((wm * 64 + mt * 16 + selr + swz) * 128);
    #pragma unroll
    for (int nt = 0; nt < 4; nt++)
        bRow[nt] = (uint32_t)((wn * 32 + nt * 8 + swz) * 128);

    const uint32_t ldOff[4] = {
        (uint32_t)((lrow4 + 0)  * 128 + ((lc16 ^ ((lrow4 + 0)  & 7)) << 4)),
        (uint32_t)((lrow4 + 32) * 128 + ((lc16 ^ ((lrow4 + 32) & 7)) << 4)),
        (uint32_t)((lrow4 + 64) * 128 + ((lc16 ^ ((lrow4 + 64) & 7)) << 4)),
        (uint32_t)((lrow4 + 96) * 128 + ((lc16 ^ ((lrow4 + 96) & 7)) << 4))
    };
    const float* aSrc = HS  + (size_t)(m0 + lrow4) * SDIMW + lc16 * 4;
    const float* bSrc = WoT + (size_t)(n0 + lrow4) * SDIMW + lc16 * 4;

    #define OG_ISSUE(kt_) do {                                                  \
        const int _s = (kt_) % 3;                                               \
        const int _k0 = (kt_) * 32;                                             \
        _Pragma("unroll")                                                       \
        for (int i = 0; i < 4; i++) {                                           \
            cp16(sbase + _s * 16384 + ldOff[i],                                 \
                 aSrc + (size_t)(i * 32) * SDIMW + _k0);                        \
            cp16(sbase + 49152 + _s * 16384 + ldOff[i],                         \
                 bSrc + (size_t)(i * 32) * SDIMW + _k0);                        \
        }                                                                       \
        cp_commit();                                                            \
    } while (0)

    OG_ISSUE(0);
    OG_ISSUE(1);

    float acc[4][4][4] = {};

    const int KT = SDIMW / 32;   // 8
    for (int kt = 0; kt < KT; kt++) {
        if (kt == KT - 1)
            asm volatile("cp.async.wait_group 0;" ::: "memory");
        else
            asm volatile("cp.async.wait_group 1;" ::: "memory");
        __syncthreads();
        if (kt + 2 < KT) OG_ISSUE(kt + 2);

        const uint32_t Asm = sbase + (kt % 3) * 16384;
        const uint32_t Bsm = sbase + 49152 + (kt % 3) * 16384;

        #pragma unroll
        for (int kh = 0; kh < 2; kh++) {
            uint32_t bf[4][4];
            #pragma unroll
            for (int nt = 0; nt < 4; nt++)
                ldm_x4(Bsm + bRow[nt] + (((kh * 4 + sel) ^ swz) << 4), bf[nt]);
            #pragma unroll
            for (int kk2 = 0; kk2 < 2; kk2++) {
                const int kk = kh * 2 + kk2;
                uint32_t af[4][4];
                #pragma unroll
                for (int mt = 0; mt < 4; mt++)
                    ldm_x4(Asm + aRow[mt] + (((kk * 2 + selc) ^ swz) << 4), af[mt]);
                #pragma unroll
                for (int mt = 0; mt < 4; mt++)
                    #pragma unroll
                    for (int nt = 0; nt < 4; nt++)
                        mma8(acc[mt][nt], af[mt], &bf[nt][kk2 * 2]);
            }
        }
    }

    const int g = lane >> 2, t = lane & 3;
    const int bb = blockIdx.y * 2 + wm;
    float psum[4][2];
    #pragma unroll
    for (int nt = 0; nt < 4; nt++) {
        const int nl = wn * 32 + nt * 8 + 2 * t;
        const float2 cv = *(const float2*)(cs + (size_t)bb * DIMW + n0 + nl);
        const float add0 = sbo[nl] + cv.x;
        const float add1 = sbo[nl + 1] + cv.y;
        float s0 = 0.f, s1 = 0.f;
        #pragma unroll
        for (int mt = 0; mt < 4; mt++) {
            const int row0 = m0 + wm * 64 + mt * 16 + g;
            #pragma unroll
            for (int rh = 0; rh < 2; rh++) {
                const int row = row0 + rh * 8;
                float2 ov = make_float2(acc[mt][nt][rh * 2 + 0] + add0,
                                        acc[mt][nt][rh * 2 + 1] + add1);
                if (roundOut) { ov.x = tf32r(ov.x); ov.y = tf32r(ov.y); }
                *(float2*)(out + (size_t)row * DIMW + n0 + nl) = ov;
                s0 += ov.x; s1 += ov.y;
            }
        }
        psum[nt][0] = s0; psum[nt][1] = s1;
    }
    if (pooled) {
        #pragma unroll
        for (int nt = 0; nt < 4; nt++) {
            #pragma unroll
            for (int o = 4; o < 32; o <<= 1) {
                psum[nt][0] += __shfl_xor_sync(0xffffffffu, psum[nt][0], o);
                psum[nt][1] += __shfl_xor_sync(0xffffffffu, psum[nt][1], o);
            }
        }
        if (lane < 4) {
            #pragma unroll
            for (int nt = 0; nt < 4; nt++) {
                const int nl = wn * 32 + nt * 8 + 2 * lane;
                float2 pv = make_float2(psum[nt][0] * (1.f / (float)SEQ),
                                        psum[nt][1] * (1.f / (float)SEQ));
                *(float2*)(pooled + (size_t)bb * DIMW + n0 + nl) = pv;
            }
        }
    }
}

// ---------------------------------------------------------------------------
__global__ __launch_bounds__(256)
void scan_kernel(const float* __restrict__ decay, const float* __restrict__ drive,
                 float* __restrict__ hs, float* __restrict__ fin)
{
    const int b = blockIdx.x;
    const int n = threadIdx.x;
    size_t base = (size_t)b * SEQ * SDIMW + n;
    float h = 0.f;
    #pragma unroll 8
    for (int s = 0; s < SEQ; s++) {
        size_t idx = base + (size_t)s * SDIMW;
        h = fmaf(decay[idx], h, drive[idx]);
        hs[idx] = tf32r(h);
    }
    fin[b * SDIMW + n] = h;
}

// ---------------------------------------------------------------------------
// cstate v3: 256 thr, CS_BG=4, grid (4, 64); n unrolled x8 for MLP=8.
// FMA order per acc is ascending n -> bit-identical to prior versions.
// ---------------------------------------------------------------------------
#define CS_BG 4
__global__ __launch_bounds__(256)
void cstate_kernel(const float* __restrict__ fin, const float* __restrict__ Ws,
                   const float* __restrict__ bs, float* __restrict__ cs)
{
    __shared__ float sf[CS_BG][SDIMW];
    const int d = blockIdx.x * 256 + threadIdx.x;
    const int b0 = blockIdx.y * CS_BG;
    {   // 4 rows x 64 float4 = 256 float4 loads, one per thread
        const int row = threadIdx.x >> 6, c4 = threadIdx.x & 63;
        *(float4*)&sf[row][c4 * 4] =
            *(const float4*)(fin + (size_t)(b0 + row) * SDIMW + c4 * 4);
    }
    __syncthreads();

    float acc[CS_BG] = {};
    #pragma unroll 4
    for (int n = 0; n < SDIMW; n += 8) {
        float w[8];
        #pragma unroll
        for (int j = 0; j < 8; j++)
            w[j] = Ws[(size_t)(n + j) * DIMW + d];
        #pragma unroll
        for (int b = 0; b < CS_BG; b++) {
            #pragma unroll
            for (int j = 0; j < 8; j++)
                acc[b] = fmaf(sf[b][n + j], w[j], acc[b]);
        }
    }
    const float bsv = bs[d];
    #pragma unroll
    for (int b = 0; b < CS_BG; b++)
        cs[(size_t)(b0 + b) * DIMW + d] = acc[b] + bsv;
}

// ---------------------------------------------------------------------------
__global__ __launch_bounds__(256)
void final_kernel(const float* __restrict__ pmean, const float* __restrict__ cs,
                  const float* __restrict__ gamma, const float* __restrict__ beta,
                  float* __restrict__ out)
{
    const int b = blockIdx.x;
    const int tid = threadIdx.x;

    float pooled[4];
    float lsum = 0.f, lsq = 0.f;
    #pragma unroll
    for (int i = 0; i < 4; i++) {
        const int d = i * 256 + tid;
        float p = cs[(size_t)b * DIMW + d] + pmean[(size_t)b * DIMW + d];
        pooled[i] = p;
        lsum += p;
        lsq  += p * p;
    }

    __shared__ float s1[8], s2[8];
    #pragma unroll
    for (int o = 16; o > 0; o >>= 1) {
        lsum += __shfl_xor_sync(0xffffffffu, lsum, o);
        lsq  += __shfl_xor_sync(0xffffffffu, lsq,  o);
    }
    if ((tid & 31) == 0) { s1[tid >> 5] = lsum; s2[tid >> 5] = lsq; }
    __syncthreads();
    float tsum = 0.f, tsq = 0.f;
    #pragma unroll
    for (int w = 0; w < 8; w++) { tsum += s1[w]; tsq += s2[w]; }

    const float mu  = tsum * (1.f / (float)DIMW);
    const float var = tsq * (1.f / (float)DIMW) - mu * mu;
    const float rstd = rsqrtf(var + EPS);

    #pragma unroll
    for (int i = 0; i < 4; i++) {
        const int d = i * 256 + tid;
        out[(size_t)b * DIMW + d] = (pooled[i] - mu) * rstd * gamma[d] + beta[d];
    }
}

// ---------------------------------------------------------------------------
extern "C" void kernel_launch(void* const* d_in, const int* in_sizes, int n_in,
                              void* d_out, int out_size)
{
    const float* X     = (const float*)d_in[0];
    const float* Wd    = (const float*)d_in[1];
    const float* bd    = (const float*)d_in[2];
    const float* Wi    = (const float*)d_in[3];
    const float* bi    = (const float*)d_in[4];
    const float* A_log = (const float*)d_in[5];
    const float* Wo    = (const float*)d_in[6];
    const float* bo    = (const float*)d_in[7];
    const float* Ws    = (const float*)d_in[8];
    const float* bs    = (const float*)d_in[9];
    const float* gamma = (const float*)d_in[10];
    const float* beta  = (const float*)d_in[11];

    float* out_repr   = (float*)d_out;                         // [B, D]
    float* out_hidden = (float*)d_out + (size_t)BATCH * DIMW;  // [B, S, D]

    float *p_decay, *p_drive, *p_hs, *p_hidden, *p_xr, *p_final, *p_cstate,
          *p_pooled, *p_wt;
    cudaGetSymbolAddress((void**)&p_decay,  g_decay);
    cudaGetSymbolAddress((void**)&p_drive,  g_drive);
    cudaGetSymbolAddress((void**)&p_hs,     g_hs);
    cudaGetSymbolAddress((void**)&p_hidden, g_hidden);
    cudaGetSymbolAddress((void**)&p_xr,     g_xr);
    cudaGetSymbolAddress((void**)&p_final,  g_final);
    cudaGetSymbolAddress((void**)&p_cstate, g_cstate);
    cudaGetSymbolAddress((void**)&p_pooled, g_pooled);
    cudaGetSymbolAddress((void**)&p_wt,     g_wt);

    cudaFuncSetAttribute(proj_mma_kernel,
                         cudaFuncAttributeMaxDynamicSharedMemorySize, PJ_SMEM);
    cudaFuncSetAttribute(outgemm_mma_kernel,
                         cudaFuncAttributeMaxDynamicSharedMemorySize, OG_SMEM);

    const size_t WSZ = (size_t)SDIMW * DIMW;
    float* WdT0 = p_wt + 0 * WSZ;
    float* WiT0 = p_wt + 1 * WSZ;
    float* WoT0 = p_wt + 2 * WSZ;
    float* WdT1 = p_wt + 3 * WSZ;
    float* WiT1 = p_wt + 4 * WSZ;
    float* WoT1 = p_wt + 5 * WSZ;

    transpose6_kernel<<<dim3(8, 32, 6), dim3(32, 8)>>>(Wd, Wi, Wo, p_wt);
    round_kernel<<<(MROWS * DIMW) / (256 * 4), 256>>>((const float4*)X,
                                                      (float4*)p_xr);

    const dim3 pjGrid(SDIMW / 64, MROWS / 128);    // (4, 128)
    const dim3 ogGrid(DIMW / 128, MROWS / 128);    // (8, 128)
    const dim3 csGrid(DIMW / 256, BATCH / CS_BG);  // (4, 64)

    // ---------------- layer 0 ----------------
    proj_mma_kernel<<<pjGrid, 256, PJ_SMEM>>>(p_xr, WdT0, WiT0, bd, bi, A_log,
                                              p_decay, p_drive);
    scan_kernel<<<BATCH, 256>>>(p_decay, p_drive, p_hs, p_final);
    cstate_kernel<<<csGrid, 256>>>(p_final, Ws, bs, p_cstate);
    outgemm_mma_kernel<<<ogGrid, 256, OG_SMEM>>>(p_hs, WoT0, bo, p_cstate,
                                                 p_hidden, nullptr, 1);

    // ---------------- layer 1 (hidden already tf32-rounded) ----------------
    proj_mma_kernel<<<pjGrid, 256, PJ_SMEM>>>(p_hidden, WdT1, WiT1, bd + SDIMW,
                                              bi + SDIMW, A_log + SDIMW,
                                              p_decay, p_drive);
    scan_kernel<<<BATCH, 256>>>(p_decay, p_drive, p_hs, p_final);
    cstate_kernel<<<csGrid, 256>>>(p_final, Ws + WSZ, bs + DIMW, p_cstate);
    outgemm_mma_kernel<<<ogGrid, 256, OG_SMEM>>>(p_hs, WoT1, bo + DIMW, p_cstate,
                                                 out_hidden, p_pooled, 0);

    // ---------------- LayerNorm ----------------
    final_kernel<<<BATCH, 256>>>(p_pooled, p_cstate, gamma, beta, out_repr);
}

// round 13
// speedup vs baseline: 1.1077x; 1.0327x over previous
#include <cuda_runtime.h>
#include <cstdint>

#define BATCH 256
#define SEQ   64
#define DIMW  1024
#define SDIMW 256
#define MROWS (BATCH*SEQ)   // 16384
#define EPS   1e-5f

// ---------------- scratch (static device globals; no runtime allocation) ----
__device__ float g_decay[MROWS * SDIMW];
__device__ float g_drive[MROWS * SDIMW];
__device__ float g_hs   [MROWS * SDIMW];
__device__ float g_hidden[(size_t)MROWS * DIMW];  // layer-0 hidden (tf32-rounded)
__device__ float g_xr    [(size_t)MROWS * DIMW];  // tf32-rounded X
__device__ float g_final [BATCH * SDIMW];
__device__ float g_cstate[BATCH * DIMW];
__device__ float g_pooled[BATCH * DIMW];
__device__ float g_wt[6 * SDIMW * DIMW];   // transposed + tf32-rounded weights

__device__ __forceinline__ float softplusf(float x) {
    float e = __expf(-fabsf(x));
    return fmaxf(x, 0.f) + __logf(1.f + e);
}
__device__ __forceinline__ float tf32r(float f) {
    uint32_t r;
    asm("cvt.rna.tf32.f32 %0, %1;" : "=r"(r) : "f"(f));
    return __uint_as_float(r);
}
__device__ __forceinline__ float4 tf32r4(float4 v) {
    return make_float4(tf32r(v.x), tf32r(v.y), tf32r(v.z), tf32r(v.w));
}
__device__ __forceinline__ uint32_t smem_u32(const void* p) {
    uint32_t a;
    asm("{ .reg .u64 t; cvta.to.shared.u64 t, %1; cvt.u32.u64 %0, t; }"
        : "=r"(a) : "l"(p));
    return a;
}
__device__ __forceinline__ void ldm_x4(uint32_t addr, uint32_t* r) {
    asm volatile("ldmatrix.sync.aligned.m8n8.x4.shared.b16 {%0,%1,%2,%3}, [%4];"
                 : "=r"(r[0]), "=r"(r[1]), "=r"(r[2]), "=r"(r[3]) : "r"(addr));
}
__device__ __forceinline__ void mma8(float* c, const uint32_t* a, const uint32_t* b) {
    asm volatile("mma.sync.aligned.m16n8k8.row.col.f32.tf32.tf32.f32 "
                 "{%0,%1,%2,%3}, {%4,%5,%6,%7}, {%8,%9}, {%0,%1,%2,%3};"
                 : "+f"(c[0]), "+f"(c[1]), "+f"(c[2]), "+f"(c[3])
                 : "r"(a[0]), "r"(a[1]), "r"(a[2]), "r"(a[3]),
                   "r"(b[0]), "r"(b[1]));
}
__device__ __forceinline__ void cp16(uint32_t dst, const void* src) {
    asm volatile("cp.async.cg.shared.global [%0], [%1], 16;"
                 :: "r"(dst), "l"(src) : "memory");
}
__device__ __forceinline__ void cp_commit() {
    asm volatile("cp.async.commit_group;" ::: "memory");
}

// ---------------------------------------------------------------------------
// elementwise tf32 rounding (X -> Xr)
// ---------------------------------------------------------------------------
__global__ __launch_bounds__(256)
void round_kernel(const float4* __restrict__ in, float4* __restrict__ out) {
    const size_t i = (size_t)blockIdx.x * 256 + threadIdx.x;
    out[i] = tf32r4(in[i]);
}

// ---------------------------------------------------------------------------
// 6 weight transposes (+ tf32 round) in one launch.
// ---------------------------------------------------------------------------
__global__ void transpose6_kernel(const float* __restrict__ Wd,
                                  const float* __restrict__ Wi,
                                  const float* __restrict__ Wo,
                                  float* __restrict__ wt) {
    __shared__ float t[32][33];
    const int z = blockIdx.z;
    const int layer = z / 3, mat = z % 3;
    const size_t WSZ = (size_t)SDIMW * DIMW;
    const float* src = (mat == 0 ? Wd : (mat == 1 ? Wi : Wo)) + layer * WSZ;
    float* dst = wt + (size_t)z * WSZ;
    int R, C, c0, r0;
    if (mat == 2) { R = SDIMW; C = DIMW; c0 = blockIdx.y * 32; r0 = blockIdx.x * 32; }
    else          { R = DIMW; C = SDIMW; c0 = blockIdx.x * 32; r0 = blockIdx.y * 32; }
    const int tx = threadIdx.x, ty = threadIdx.y;
    #pragma unroll
    for (int k = 0; k < 4; k++)
        t[ty + 8 * k][tx] = src[(size_t)(r0 + ty + 8 * k) * C + c0 + tx];
    __syncthreads();
    #pragma unroll
    for (int k = 0; k < 4; k++)
        dst[(size_t)(c0 + ty + 8 * k) * R + r0 + tx] = tf32r(t[tx][ty + 8 * k]);
}

// ---------------------------------------------------------------------------
// proj with cp.async 3-stage (R12-proven): decay/drive[M,256]
// ---------------------------------------------------------------------------
#define PJ_SMEM (98304 + 3 * 64 * 4)
__global__ __launch_bounds__(256)
void proj_mma_kernel(const float* __restrict__ X,
                     const float* __restrict__ WdT, const float* __restrict__ WiT,
                     const float* __restrict__ bd, const float* __restrict__ bi,
                     const float* __restrict__ A_log,
                     float* __restrict__ decay, float* __restrict__ drive)
{
    extern __shared__ char smem[];
    const uint32_t sbase = smem_u32(smem);
    const int tid = threadIdx.x, wid = tid >> 5, lane = tid & 31;
    const int wm = wid & 3, wn = wid >> 2;
    const int m0 = blockIdx.y * 128, n0 = blockIdx.x * 64;

    float* sbd = (float*)(smem + 98304);
    float* sbi = sbd + 64;
    float* ssa = sbi + 64;
    if (tid < 64) {
        sbd[tid] = bd[n0 + tid];
        sbi[tid] = bi[n0 + tid];
        ssa[tid] = softplusf(A_log[n0 + tid]);
    }

    const int lrow4 = tid >> 3, lc16 = tid & 7;
    const int swz = lane & 7, sel = lane >> 3;
    const int selr = (sel & 1) * 8, selc = sel >> 1;

    uint32_t aRow[2], bRow[4];
    #pragma unroll
    for (int mt = 0; mt < 2; mt++)
        aRow[mt] = (uint32_t)((wm * 32 + mt * 16 + selr + swz) * 128);
    #pragma unroll
    for (int nt = 0; nt < 4; nt++)
        bRow[nt] = (uint32_t)((wn * 32 + nt * 8 + swz) * 128);

    const uint32_t ldOffA[4] = {
        (uint32_t)((lrow4 + 0)  * 128 + ((lc16 ^ ((lrow4 + 0)  & 7)) << 4)),
        (uint32_t)((lrow4 + 32) * 128 + ((lc16 ^ ((lrow4 + 32) & 7)) << 4)),
        (uint32_t)((lrow4 + 64) * 128 + ((lc16 ^ ((lrow4 + 64) & 7)) << 4)),
        (uint32_t)((lrow4 + 96) * 128 + ((lc16 ^ ((lrow4 + 96) & 7)) << 4))
    };
    const float* aSrc = X   + (size_t)(m0 + lrow4) * DIMW + lc16 * 4;
    const float* dSrc = WdT + (size_t)(n0 + lrow4) * DIMW + lc16 * 4;
    const float* iSrc = WiT + (size_t)(n0 + lrow4) * DIMW + lc16 * 4;

    #define PJ_ISSUE(kt_) do {                                                  \
        const int _s = (kt_) % 3;                                               \
        const int _k0 = (kt_) * 32;                                             \
        _Pragma("unroll")                                                       \
        for (int i = 0; i < 4; i++)                                             \
            cp16(sbase + _s * 16384 + ldOffA[i],                                \
                 aSrc + (size_t)(i * 32) * DIMW + _k0);                         \
        _Pragma("unroll")                                                       \
        for (int i = 0; i < 2; i++) {                                           \
            cp16(sbase + 49152 + _s * 8192 + ldOffA[i],                         \
                 dSrc + (size_t)(i * 32) * DIMW + _k0);                         \
            cp16(sbase + 73728 + _s * 8192 + ldOffA[i],                         \
                 iSrc + (size_t)(i * 32) * DIMW + _k0);                         \
        }                                                                       \
        cp_commit();                                                            \
    } while (0)

    PJ_ISSUE(0);
    PJ_ISSUE(1);

    float accD[2][4][4] = {};
    float accI[2][4][4] = {};

    const int KT = DIMW / 32;   // 32
    for (int kt = 0; kt < KT; kt++) {
        if (kt == KT - 1)
            asm volatile("cp.async.wait_group 0;" ::: "memory");
        else
            asm volatile("cp.async.wait_group 1;" ::: "memory");
        __syncthreads();
        if (kt + 2 < KT) PJ_ISSUE(kt + 2);

        const uint32_t Asm  = sbase + (kt % 3) * 16384;
        const uint32_t Bdsm = sbase + 49152 + (kt % 3) * 8192;
        const uint32_t Bism = sbase + 73728 + (kt % 3) * 8192;

        uint32_t af[2][4][4];
        #pragma unroll
        for (int mt = 0; mt < 2; mt++)
            #pragma unroll
            for (int kk = 0; kk < 4; kk++)
                ldm_x4(Asm + aRow[mt] + (((kk * 2 + selc) ^ swz) << 4), af[mt][kk]);

        #pragma unroll
        for (int out = 0; out < 2; out++) {
            const uint32_t Bsm = out ? Bism : Bdsm;
            #pragma unroll
            for (int kh = 0; kh < 2; kh++) {
                uint32_t bf[4][4];
                #pragma unroll
                for (int nt = 0; nt < 4; nt++)
                    ldm_x4(Bsm + bRow[nt] + (((kh * 4 + sel) ^ swz) << 4), bf[nt]);
                #pragma unroll
                for (int kk2 = 0; kk2 < 2; kk2++)
                    #pragma unroll
                    for (int mt = 0; mt < 2; mt++)
                        #pragma unroll
                        for (int nt = 0; nt < 4; nt++)
                            mma8(out ? accI[mt][nt] : accD[mt][nt],
                                 af[mt][kh * 2 + kk2], &bf[nt][kk2 * 2]);
            }
        }
    }

    const int g = lane >> 2, t = lane & 3;
    #pragma unroll
    for (int mt = 0; mt < 2; mt++) {
        const int row0 = m0 + wm * 32 + mt * 16 + g;
        #pragma unroll
        for (int nt = 0; nt < 4; nt++) {
            const int nl = wn * 32 + nt * 8 + 2 * t;
            const float b0 = sbd[nl], b1 = sbd[nl + 1];
            const float i0 = sbi[nl], i1 = sbi[nl + 1];
            const float a0 = ssa[nl], a1 = ssa[nl + 1];
            #pragma unroll
            for (int rh = 0; rh < 2; rh++) {
                const int row = row0 + rh * 8;
                const float de0 = softplusf(accD[mt][nt][rh * 2 + 0] + b0);
                const float de1 = softplusf(accD[mt][nt][rh * 2 + 1] + b1);
                float2 dec = make_float2(__expf(-de0 * a0), __expf(-de1 * a1));
                float2 drv = make_float2(de0 * (accI[mt][nt][rh * 2 + 0] + i0),
                                         de1 * (accI[mt][nt][rh * 2 + 1] + i1));
                *(float2*)(decay + (size_t)row * SDIMW + n0 + nl) = dec;
                *(float2*)(drive + (size_t)row * SDIMW + n0 + nl) = drv;
            }
        }
    }
}

// ---------------------------------------------------------------------------
// outgemm v2: CTA 128m x 64n, warp 64m x 16n (8 warps 2m x 4n), 2 CTAs/SM.
// cp.async 3-stage. Accumulation order per element unchanged (bit-identical).
// smem: A 3x16KB @0, B 3x8KB @49152, bo(64) @73728.
// ---------------------------------------------------------------------------
#define OG_SMEM (73728 + 64 * 4)
__global__ __launch_bounds__(256, 2)
void outgemm_mma_kernel(const float* __restrict__ HS, const float* __restrict__ WoT,
                        const float* __restrict__ bo, const float* __restrict__ cs,
                        float* __restrict__ out, float* __restrict__ pooled,
                        int roundOut)
{
    extern __shared__ char smem[];
    const uint32_t sbase = smem_u32(smem);
    const int tid = threadIdx.x, wid = tid >> 5, lane = tid & 31;
    const int wm = wid & 1, wn = wid >> 1;
    const int m0 = blockIdx.y * 128, n0 = blockIdx.x * 64;

    float* sbo = (float*)(smem + 73728);
    if (tid < 64) sbo[tid] = bo[n0 + tid];

    const int lrow4 = tid >> 3, lc16 = tid & 7;
    const int swz = lane & 7, sel = lane >> 3;
    const int selr = (sel & 1) * 8, selc = sel >> 1;

    uint32_t aRow[4], bRow[2];
    #pragma unroll
    for (int mt = 0; mt < 4; mt++)
        aRow[mt] = (uint32_t)((wm * 64 + mt * 16 + selr + swz) * 128);
    #pragma unroll
    for (int nt = 0; nt < 2; nt++)
        bRow[nt] = (uint32_t)((wn * 16 + nt * 8 + swz) * 128);

    const uint32_t ldOff[4] = {
        (uint32_t)((lrow4 + 0)  * 128 + ((lc16 ^ ((lrow4 + 0)  & 7)) << 4)),
        (uint32_t)((lrow4 + 32) * 128 + ((lc16 ^ ((lrow4 + 32) & 7)) << 4)),
        (uint32_t)((lrow4 + 64) * 128 + ((lc16 ^ ((lrow4 + 64) & 7)) << 4)),
        (uint32_t)((lrow4 + 96) * 128 + ((lc16 ^ ((lrow4 + 96) & 7)) << 4))
    };
    const float* aSrc = HS  + (size_t)(m0 + lrow4) * SDIMW + lc16 * 4;
    const float* bSrc = WoT + (size_t)(n0 + lrow4) * SDIMW + lc16 * 4;

    #define OG_ISSUE(kt_) do {                                                  \
        const int _s = (kt_) % 3;                                               \
        const int _k0 = (kt_) * 32;                                             \
        _Pragma("unroll")                                                       \
        for (int i = 0; i < 4; i++)                                             \
            cp16(sbase + _s * 16384 + ldOff[i],                                 \
                 aSrc + (size_t)(i * 32) * SDIMW + _k0);                        \
        _Pragma("unroll")                                                       \
        for (int i = 0; i < 2; i++)                                             \
            cp16(sbase + 49152 + _s * 8192 + ldOff[i],                          \
                 bSrc + (size_t)(i * 32) * SDIMW + _k0);                        \
        cp_commit();                                                            \
    } while (0)

    OG_ISSUE(0);
    OG_ISSUE(1);

    float acc[4][2][4] = {};

    const int KT = SDIMW / 32;   // 8
    for (int kt = 0; kt < KT; kt++) {
        if (kt == KT - 1)
            asm volatile("cp.async.wait_group 0;" ::: "memory");
        else
            asm volatile("cp.async.wait_group 1;" ::: "memory");
        __syncthreads();
        if (kt + 2 < KT) OG_ISSUE(kt + 2);

        const uint32_t Asm = sbase + (kt % 3) * 16384;
        const uint32_t Bsm = sbase + 49152 + (kt % 3) * 8192;

        #pragma unroll
        for (int kh = 0; kh < 2; kh++) {
            uint32_t bf[2][4];
            #pragma unroll
            for (int nt = 0; nt < 2; nt++)
                ldm_x4(Bsm + bRow[nt] + (((kh * 4 + sel) ^ swz) << 4), bf[nt]);
            #pragma unroll
            for (int kk2 = 0; kk2 < 2; kk2++) {
                const int kk = kh * 2 + kk2;
                uint32_t af[4][4];
                #pragma unroll
                for (int mt = 0; mt < 4; mt++)
                    ldm_x4(Asm + aRow[mt] + (((kk * 2 + selc) ^ swz) << 4), af[mt]);
                #pragma unroll
                for (int mt = 0; mt < 4; mt++)
                    #pragma unroll
                    for (int nt = 0; nt < 2; nt++)
                        mma8(acc[mt][nt], af[mt], &bf[nt][kk2 * 2]);
            }
        }
    }

    const int g = lane >> 2, t = lane & 3;
    const int bb = blockIdx.y * 2 + wm;
    float psum[2][2];
    #pragma unroll
    for (int nt = 0; nt < 2; nt++) {
        const int nl = wn * 16 + nt * 8 + 2 * t;
        const float2 cv = *(const float2*)(cs + (size_t)bb * DIMW + n0 + nl);
        const float add0 = sbo[nl] + cv.x;
        const float add1 = sbo[nl + 1] + cv.y;
        float s0 = 0.f, s1 = 0.f;
        #pragma unroll
        for (int mt = 0; mt < 4; mt++) {
            const int row0 = m0 + wm * 64 + mt * 16 + g;
            #pragma unroll
            for (int rh = 0; rh < 2; rh++) {
                const int row = row0 + rh * 8;
                float2 ov = make_float2(acc[mt][nt][rh * 2 + 0] + add0,
                                        acc[mt][nt][rh * 2 + 1] + add1);
                if (roundOut) { ov.x = tf32r(ov.x); ov.y = tf32r(ov.y); }
                *(float2*)(out + (size_t)row * DIMW + n0 + nl) = ov;
                s0 += ov.x; s1 += ov.y;
            }
        }
        psum[nt][0] = s0; psum[nt][1] = s1;
    }
    if (pooled) {
        #pragma unroll
        for (int nt = 0; nt < 2; nt++) {
            #pragma unroll
            for (int o = 4; o < 32; o <<= 1) {
                psum[nt][0] += __shfl_xor_sync(0xffffffffu, psum[nt][0], o);
                psum[nt][1] += __shfl_xor_sync(0xffffffffu, psum[nt][1], o);
            }
        }
        if (lane < 4) {
            #pragma unroll
            for (int nt = 0; nt < 2; nt++) {
                const int nl = wn * 16 + nt * 8 + 2 * lane;
                float2 pv = make_float2(psum[nt][0] * (1.f / (float)SEQ),
                                        psum[nt][1] * (1.f / (float)SEQ));
                *(float2*)(pooled + (size_t)bb * DIMW + n0 + nl) = pv;
            }
        }
    }
}

// ---------------------------------------------------------------------------
__global__ __launch_bounds__(256)
void scan_kernel(const float* __restrict__ decay, const float* __restrict__ drive,
                 float* __restrict__ hs, float* __restrict__ fin)
{
    const int b = blockIdx.x;
    const int n = threadIdx.x;
    size_t base = (size_t)b * SEQ * SDIMW + n;
    float h = 0.f;
    #pragma unroll 8
    for (int s = 0; s < SEQ; s++) {
        size_t idx = base + (size_t)s * SDIMW;
        h = fmaf(decay[idx], h, drive[idx]);
        hs[idx] = tf32r(h);
    }
    fin[b * SDIMW + n] = h;
}

// ---------------------------------------------------------------------------
// cstate v3 (R12-proven): 256 thr, CS_BG=4, n unrolled x8.
// ---------------------------------------------------------------------------
#define CS_BG 4
__global__ __launch_bounds__(256)
void cstate_kernel(const float* __restrict__ fin, const float* __restrict__ Ws,
                   const float* __restrict__ bs, float* __restrict__ cs)
{
    __shared__ float sf[CS_BG][SDIMW];
    const int d = blockIdx.x * 256 + threadIdx.x;
    const int b0 = blockIdx.y * CS_BG;
    {
        const int row = threadIdx.x >> 6, c4 = threadIdx.x & 63;
        *(float4*)&sf[row][c4 * 4] =
            *(const float4*)(fin + (size_t)(b0 + row) * SDIMW + c4 * 4);
    }
    __syncthreads();

    float acc[CS_BG] = {};
    #pragma unroll 4
    for (int n = 0; n < SDIMW; n += 8) {
        float w[8];
        #pragma unroll
        for (int j = 0; j < 8; j++)
            w[j] = Ws[(size_t)(n + j) * DIMW + d];
        #pragma unroll
        for (int b = 0; b < CS_BG; b++) {
            #pragma unroll
            for (int j = 0; j < 8; j++)
                acc[b] = fmaf(sf[b][n + j], w[j], acc[b]);
        }
    }
    const float bsv = bs[d];
    #pragma unroll
    for (int b = 0; b < CS_BG; b++)
        cs[(size_t)(b0 + b) * DIMW + d] = acc[b] + bsv;
}

// ---------------------------------------------------------------------------
__global__ __launch_bounds__(256)
void final_kernel(const float* __restrict__ pmean, const float* __restrict__ cs,
                  const float* __restrict__ gamma, const float* __restrict__ beta,
                  float* __restrict__ out)
{
    const int b = blockIdx.x;
    const int tid = threadIdx.x;

    float pooled[4];
    float lsum = 0.f, lsq = 0.f;
    #pragma unroll
    for (int i = 0; i < 4; i++) {
        const int d = i * 256 + tid;
        float p = cs[(size_t)b * DIMW + d] + pmean[(size_t)b * DIMW + d];
        pooled[i] = p;
        lsum += p;
        lsq  += p * p;
    }

    __shared__ float s1[8], s2[8];
    #pragma unroll
    for (int o = 16; o > 0; o >>= 1) {
        lsum += __shfl_xor_sync(0xffffffffu, lsum, o);
        lsq  += __shfl_xor_sync(0xffffffffu, lsq,  o);
    }
    if ((tid & 31) == 0) { s1[tid >> 5] = lsum; s2[tid >> 5] = lsq; }
    __syncthreads();
    float tsum = 0.f, tsq = 0.f;
    #pragma unroll
    for (int w = 0; w < 8; w++) { tsum += s1[w]; tsq += s2[w]; }

    const float mu  = tsum * (1.f / (float)DIMW);
    const float var = tsq * (1.f / (float)DIMW) - mu * mu;
    const float rstd = rsqrtf(var + EPS);

    #pragma unroll
    for (int i = 0; i < 4; i++) {
        const int d = i * 256 + tid;
        out[(size_t)b * DIMW + d] = (pooled[i] - mu) * rstd * gamma[d] + beta[d];
    }
}

// ---------------------------------------------------------------------------
extern "C" void kernel_launch(void* const* d_in, const int* in_sizes, int n_in,
                              void* d_out, int out_size)
{
    const float* X     = (const float*)d_in[0];
    const float* Wd    = (const float*)d_in[1];
    const float* bd    = (const float*)d_in[2];
    const float* Wi    = (const float*)d_in[3];
    const float* bi    = (const float*)d_in[4];
    const float* A_log = (const float*)d_in[5];
    const float* Wo    = (const float*)d_in[6];
    const float* bo    = (const float*)d_in[7];
    const float* Ws    = (const float*)d_in[8];
    const float* bs    = (const float*)d_in[9];
    const float* gamma = (const float*)d_in[10];
    const float* beta  = (const float*)d_in[11];

    float* out_repr   = (float*)d_out;                         // [B, D]
    float* out_hidden = (float*)d_out + (size_t)BATCH * DIMW;  // [B, S, D]

    float *p_decay, *p_drive, *p_hs, *p_hidden, *p_xr, *p_final, *p_cstate,
          *p_pooled, *p_wt;
    cudaGetSymbolAddress((void**)&p_decay,  g_decay);
    cudaGetSymbolAddress((void**)&p_drive,  g_drive);
    cudaGetSymbolAddress((void**)&p_hs,     g_hs);
    cudaGetSymbolAddress((void**)&p_hidden, g_hidden);
    cudaGetSymbolAddress((void**)&p_xr,     g_xr);
    cudaGetSymbolAddress((void**)&p_final,  g_final);
    cudaGetSymbolAddress((void**)&p_cstate, g_cstate);
    cudaGetSymbolAddress((void**)&p_pooled, g_pooled);
    cudaGetSymbolAddress((void**)&p_wt,     g_wt);

    cudaFuncSetAttribute(proj_mma_kernel,
                         cudaFuncAttributeMaxDynamicSharedMemorySize, PJ_SMEM);
    cudaFuncSetAttribute(outgemm_mma_kernel,
                         cudaFuncAttributeMaxDynamicSharedMemorySize, OG_SMEM);

    const size_t WSZ = (size_t)SDIMW * DIMW;
    float* WdT0 = p_wt + 0 * WSZ;
    float* WiT0 = p_wt + 1 * WSZ;
    float* WoT0 = p_wt + 2 * WSZ;
    float* WdT1 = p_wt + 3 * WSZ;
    float* WiT1 = p_wt + 4 * WSZ;
    float* WoT1 = p_wt + 5 * WSZ;

    transpose6_kernel<<<dim3(8, 32, 6), dim3(32, 8)>>>(Wd, Wi, Wo, p_wt);
    round_kernel<<<(MROWS * DIMW) / (256 * 4), 256>>>((const float4*)X,
                                                      (float4*)p_xr);

    const dim3 pjGrid(SDIMW / 64, MROWS / 128);    // (4, 128)
    const dim3 ogGrid(DIMW / 64, MROWS / 128);     // (16, 128)
    const dim3 csGrid(DIMW / 256, BATCH / CS_BG);  // (4, 64)

    // ---------------- layer 0 ----------------
    proj_mma_kernel<<<pjGrid, 256, PJ_SMEM>>>(p_xr, WdT0, WiT0, bd, bi, A_log,
                                              p_decay, p_drive);
    scan_kernel<<<BATCH, 256>>>(p_decay, p_drive, p_hs, p_final);
    cstate_kernel<<<csGrid, 256>>>(p_final, Ws, bs, p_cstate);
    outgemm_mma_kernel<<<ogGrid, 256, OG_SMEM>>>(p_hs, WoT0, bo, p_cstate,
                                                 p_hidden, nullptr, 1);

    // ---------------- layer 1 (hidden already tf32-rounded) ----------------
    proj_mma_kernel<<<pjGrid, 256, PJ_SMEM>>>(p_hidden, WdT1, WiT1, bd + SDIMW,
                                              bi + SDIMW, A_log + SDIMW,
                                              p_decay, p_drive);
    scan_kernel<<<BATCH, 256>>>(p_decay, p_drive, p_hs, p_final);
    cstate_kernel<<<csGrid, 256>>>(p_final, Ws + WSZ, bs + DIMW, p_cstate);
    outgemm_mma_kernel<<<ogGrid, 256, OG_SMEM>>>(p_hs, WoT1, bo + DIMW, p_cstate,
                                                 out_hidden, p_pooled, 0);

    // ---------------- LayerNorm ----------------
    final_kernel<<<BATCH, 256>>>(p_pooled, p_cstate, gamma, beta, out_repr);
}